// round 1
// baseline (speedup 1.0000x reference)
#include <cuda_runtime.h>
#include <cuda_bf16.h>
#include <math.h>

// ---------------------------------------------------------------------------
// Actor_10505490006716 — MTRNN actor, pruned dataflow:
//   gates0/1 = [x0;x1] @ Wih1^T + b1          (8192 x 2048 x K=3072)  103 GF
//   h1,c1    = cell(gates0, c=0), relu
//   gates1  += h1 @ Whh1^T                    (4096 x 2048 x 512)
//   h1       = cell(gates1, c1), relu
//   h2 = cellz(h1 @ Wih2^T + b2)  h3 = cellz(h2 @ Wih3^T + b3)
//   h4 = cellz(h3 @ Wih4^T + b4)
//   out = (u < relu(h4 @ Wout^T + bout)) ? 1 : 0
// cell1 at t=2,3 is dead (h2/h3/h4 are each computed once); skipped entirely.
// ---------------------------------------------------------------------------

#define BATCH 4096
#define HID   512
#define G4    2048            // 4*H
#define INDIM 3072
#define ACT   512

// scratch (device globals: allocation-free per harness rules)
__device__ float g_X[(size_t)8192 * 3072];     // packed [x_t0 ; x_t1]
__device__ float g_G[(size_t)8192 * 2048];     // gates (t0 rows, t1 rows)
__device__ float g_h1[(size_t)BATCH * HID];
__device__ float g_c1[(size_t)BATCH * HID];
__device__ float g_hA[(size_t)BATCH * HID];
__device__ float g_hB[(size_t)BATCH * HID];

// ---------------------------------------------------------------------------
// pack X = concat(state[:,t], goal[:,t]) for t in {0,1}; rows 0..4095 = t0,
// rows 4096..8191 = t1. float4 granularity.
// ---------------------------------------------------------------------------
__global__ void pack_x_kernel(const float* __restrict__ state,
                              const float* __restrict__ goal,
                              float* __restrict__ X)
{
    const int COL4 = INDIM / 4;                     // 768
    size_t idx = (size_t)blockIdx.x * blockDim.x + threadIdx.x;
    if (idx >= (size_t)8192 * COL4) return;
    int row  = (int)(idx / COL4);
    int col  = (int)(idx % COL4) * 4;
    int b    = row & 4095;
    int t    = row >> 12;                           // 0 or 1
    float4 v;
    if (col < 2048) {
        v = *(const float4*)(state + ((size_t)(b * 4 + t)) * 2048 + col);
    } else {
        v = *(const float4*)(goal + ((size_t)(b * 4 + t)) * 1024 + (col - 2048));
    }
    *(float4*)(X + (size_t)row * INDIM + col) = v;
}

// ---------------------------------------------------------------------------
// SGEMM (NT): C[M,N] = A[M,K] * B[N,K]^T   (+ epilogue per mode)
//   mode 0: C = acc + bias1[n] (+ bias2[n])
//   mode 1: C += acc
//   mode 2: Out[m,n] = (U[m,n] < max(acc + bias1[n], 0)) ? 1 : 0
// BM=BN=128, BK=16, 256 threads, 8x8 per thread. All dims divide tiles.
// ---------------------------------------------------------------------------
#define BM 128
#define BN 128
#define BK 16

__global__ void __launch_bounds__(256, 2)
sgemm_nt(const float* __restrict__ A, const float* __restrict__ B,
         float* __restrict__ C,
         const float* __restrict__ bias1, const float* __restrict__ bias2,
         const float* __restrict__ U, float* __restrict__ Out,
         int M, int N, int K, int mode)
{
    __shared__ float As[BK][BM + 4];
    __shared__ float Bs[BK][BN + 4];

    const int bm  = blockIdx.y * BM;
    const int bn  = blockIdx.x * BN;
    const int tid = threadIdx.x;
    const int tx  = tid & 15;
    const int ty  = tid >> 4;

    const int lr = tid >> 2;          // 0..63
    const int lc = (tid & 3) << 2;    // 0,4,8,12

    const float* Ap = A + (size_t)(bm + lr) * K + lc;
    const float* Bp = B + (size_t)(bn + lr) * K + lc;
    const size_t step64 = (size_t)64 * K;

    float acc[8][8];
#pragma unroll
    for (int i = 0; i < 8; i++)
#pragma unroll
        for (int j = 0; j < 8; j++) acc[i][j] = 0.f;

    for (int k0 = 0; k0 < K; k0 += BK) {
        float4 a0 = *(const float4*)(Ap + k0);
        float4 a1 = *(const float4*)(Ap + step64 + k0);
        float4 b0 = *(const float4*)(Bp + k0);
        float4 b1 = *(const float4*)(Bp + step64 + k0);

        As[lc + 0][lr] = a0.x; As[lc + 1][lr] = a0.y;
        As[lc + 2][lr] = a0.z; As[lc + 3][lr] = a0.w;
        As[lc + 0][lr + 64] = a1.x; As[lc + 1][lr + 64] = a1.y;
        As[lc + 2][lr + 64] = a1.z; As[lc + 3][lr + 64] = a1.w;

        Bs[lc + 0][lr] = b0.x; Bs[lc + 1][lr] = b0.y;
        Bs[lc + 2][lr] = b0.z; Bs[lc + 3][lr] = b0.w;
        Bs[lc + 0][lr + 64] = b1.x; Bs[lc + 1][lr + 64] = b1.y;
        Bs[lc + 2][lr + 64] = b1.z; Bs[lc + 3][lr + 64] = b1.w;

        __syncthreads();
#pragma unroll
        for (int kk = 0; kk < BK; kk++) {
            float ar[8], br[8];
#pragma unroll
            for (int i = 0; i < 8; i++) ar[i] = As[kk][ty * 8 + i];
#pragma unroll
            for (int j = 0; j < 8; j++) br[j] = Bs[kk][tx * 8 + j];
#pragma unroll
            for (int i = 0; i < 8; i++)
#pragma unroll
                for (int j = 0; j < 8; j++)
                    acc[i][j] = fmaf(ar[i], br[j], acc[i][j]);
        }
        __syncthreads();
    }

    const int row0 = bm + ty * 8;
    const int col0 = bn + tx * 8;

    if (mode == 0) {
        float bv[8];
#pragma unroll
        for (int j = 0; j < 8; j++) {
            bv[j] = bias1[col0 + j];
            if (bias2) bv[j] += bias2[col0 + j];
        }
#pragma unroll
        for (int i = 0; i < 8; i++) {
            float* Cp = C + (size_t)(row0 + i) * N + col0;
#pragma unroll
            for (int j = 0; j < 8; j++) Cp[j] = acc[i][j] + bv[j];
        }
    } else if (mode == 1) {
#pragma unroll
        for (int i = 0; i < 8; i++) {
            float* Cp = C + (size_t)(row0 + i) * N + col0;
#pragma unroll
            for (int j = 0; j < 8; j++) Cp[j] += acc[i][j];
        }
    } else {
        float bv[8];
#pragma unroll
        for (int j = 0; j < 8; j++) bv[j] = bias1[col0 + j];
#pragma unroll
        for (int i = 0; i < 8; i++) {
            const float* Up = U + (size_t)(row0 + i) * N + col0;
            float* Op = Out + (size_t)(row0 + i) * N + col0;
#pragma unroll
            for (int j = 0; j < 8; j++) {
                float p = fmaxf(acc[i][j] + bv[j], 0.f);
                Op[j] = (Up[j] < p) ? 1.0f : 0.0f;
            }
        }
    }
}

// ---------------------------------------------------------------------------
// LSTM cell elementwise epilogues. gates row layout: [i | f | g | o], 512 each.
// ---------------------------------------------------------------------------
__device__ __forceinline__ float sigm(float x) { return 1.0f / (1.0f + expf(-x)); }

// c_prev = 0 variant: c = sig(i)*tanh(g); h = sig(o)*tanh(c); relu both.
__global__ void cell_zero_kernel(const float* __restrict__ gates,
                                 float* __restrict__ h,
                                 float* __restrict__ c /* nullable */)
{
    int idx = blockIdx.x * 256 + threadIdx.x;
    if (idx >= BATCH * HID) return;
    int m = idx >> 9;
    int n = idx & 511;
    const float* gr = gates + (size_t)m * G4;
    float gi = gr[n];
    float gg = gr[n + 1024];
    float go = gr[n + 1536];
    float cn = sigm(gi) * tanhf(gg);
    float hn = sigm(go) * tanhf(cn);
    h[idx] = fmaxf(hn, 0.f);
    if (c) c[idx] = fmaxf(cn, 0.f);
}

// full step: c = sig(f)*c_prev + sig(i)*tanh(g); h = sig(o)*tanh(c); relu h.
__global__ void cell_step_kernel(const float* __restrict__ gates,
                                 const float* __restrict__ cprev,
                                 float* __restrict__ h)
{
    int idx = blockIdx.x * 256 + threadIdx.x;
    if (idx >= BATCH * HID) return;
    int m = idx >> 9;
    int n = idx & 511;
    const float* gr = gates + (size_t)m * G4;
    float gi = gr[n];
    float gf = gr[n + 512];
    float gg = gr[n + 1024];
    float go = gr[n + 1536];
    float cn = sigm(gf) * cprev[idx] + sigm(gi) * tanhf(gg);
    float hn = sigm(go) * tanhf(cn);
    h[idx] = fmaxf(hn, 0.f);
}

// ---------------------------------------------------------------------------
extern "C" void kernel_launch(void* const* d_in, const int* in_sizes, int n_in,
                              void* d_out, int out_size)
{
    const float* state = (const float*)d_in[0];
    const float* goal  = (const float*)d_in[1];
    const float* u     = (const float*)d_in[2];
    const float* Wih1  = (const float*)d_in[3];
    const float* Whh1  = (const float*)d_in[4];
    const float* bih1  = (const float*)d_in[5];
    const float* bhh1  = (const float*)d_in[6];
    const float* Wih2  = (const float*)d_in[7];
    const float* bih2  = (const float*)d_in[9];
    const float* bhh2  = (const float*)d_in[10];
    const float* Wih3  = (const float*)d_in[11];
    const float* bih3  = (const float*)d_in[13];
    const float* bhh3  = (const float*)d_in[14];
    const float* Wih4  = (const float*)d_in[15];
    const float* bih4  = (const float*)d_in[17];
    const float* bhh4  = (const float*)d_in[18];
    const float* Wout  = (const float*)d_in[19];
    const float* bout  = (const float*)d_in[20];
    float* out = (float*)d_out;

    float *X, *G, *h1, *c1, *hA, *hB;
    cudaGetSymbolAddress((void**)&X,  g_X);
    cudaGetSymbolAddress((void**)&G,  g_G);
    cudaGetSymbolAddress((void**)&h1, g_h1);
    cudaGetSymbolAddress((void**)&c1, g_c1);
    cudaGetSymbolAddress((void**)&hA, g_hA);
    cudaGetSymbolAddress((void**)&hB, g_hB);

    float* G1 = G + (size_t)4096 * 2048;   // t=1 gate rows

    // pack x0,x1
    {
        size_t total = (size_t)8192 * (INDIM / 4);
        int blocks = (int)((total + 255) / 256);
        pack_x_kernel<<<blocks, 256>>>(state, goal, X);
    }

    // big GEMM: gates(t0,t1) = X @ Wih1^T + (bih1+bhh1)
    sgemm_nt<<<dim3(G4 / BN, 8192 / BM), 256>>>(
        X, Wih1, G, bih1, bhh1, nullptr, nullptr, 8192, G4, INDIM, 0);

    // cell1 @ t=0
    cell_zero_kernel<<<(BATCH * HID) / 256, 256>>>(G, h1, c1);

    // gates(t1) += h1 @ Whh1^T
    sgemm_nt<<<dim3(G4 / BN, BATCH / BM), 256>>>(
        h1, Whh1, G1, nullptr, nullptr, nullptr, nullptr, BATCH, G4, HID, 1);

    // cell1 @ t=1 (overwrites h1)
    cell_step_kernel<<<(BATCH * HID) / 256, 256>>>(G1, c1, h1);

    // layer 2
    sgemm_nt<<<dim3(G4 / BN, BATCH / BM), 256>>>(
        h1, Wih2, G, bih2, bhh2, nullptr, nullptr, BATCH, G4, HID, 0);
    cell_zero_kernel<<<(BATCH * HID) / 256, 256>>>(G, hA, nullptr);

    // layer 3
    sgemm_nt<<<dim3(G4 / BN, BATCH / BM), 256>>>(
        hA, Wih3, G, bih3, bhh3, nullptr, nullptr, BATCH, G4, HID, 0);
    cell_zero_kernel<<<(BATCH * HID) / 256, 256>>>(G, hB, nullptr);

    // layer 4
    sgemm_nt<<<dim3(G4 / BN, BATCH / BM), 256>>>(
        hB, Wih4, G, bih4, bhh4, nullptr, nullptr, BATCH, G4, HID, 0);
    cell_zero_kernel<<<(BATCH * HID) / 256, 256>>>(G, hA, nullptr);

    // output head: out = (u < relu(hA @ Wout^T + bout))
    sgemm_nt<<<dim3(ACT / BN, BATCH / BM), 256>>>(
        hA, Wout, nullptr, bout, nullptr, u, out, BATCH, ACT, HID, 2);
}